// round 14
// baseline (speedup 1.0000x reference)
#include <cuda_runtime.h>
#include <cstdint>

typedef unsigned long long u64;

#define B_  2
#define T_  2560
#define C_  768
#define H_  12
#define HD_ 64
#define M_  (B_*T_)   // 5120

// ---- scratch (static device arrays; no allocation) ----
__device__ float g_Q[B_*H_*T_*HD_];
__device__ float g_K[B_*H_*T_*HD_];
__device__ float g_V[B_*H_*HD_*T_];   // TRANSPOSED: [bh][d][t]
__device__ float g_Y[B_*T_*C_];

// ---- packed f32x2 helpers (Blackwell FFMA2) ----
__device__ __forceinline__ u64 fma2(u64 a, u64 b, u64 c) {
    u64 d; asm("fma.rn.f32x2 %0, %1, %2, %3;" : "=l"(d) : "l"(a), "l"(b), "l"(c)); return d;
}
__device__ __forceinline__ u64 pack2(float x, float y) {
    u64 d; asm("mov.b64 %0, {%1, %2};" : "=l"(d) : "f"(x), "f"(y)); return d;
}
__device__ __forceinline__ float2 unpack2(u64 v) {
    float2 r; asm("mov.b64 {%0, %1}, %2;" : "=f"(r.x), "=f"(r.y) : "l"(v)); return r;
}
__device__ __forceinline__ float ex2f_(float x) {
    float y; asm("ex2.approx.ftz.f32 %0, %1;" : "=f"(y) : "f"(x)); return y;
}
__device__ __forceinline__ void cpa16(uint32_t dst, const void* src) {
    asm volatile("cp.async.ca.shared.global [%0], [%1], 16;" :: "r"(dst), "l"(src) : "memory");
}
__device__ __forceinline__ void cpa_commit() {
    asm volatile("cp.async.commit_group;" ::: "memory");
}
__device__ __forceinline__ void cpa_wait0() {
    asm volatile("cp.async.wait_group 0;" ::: "memory");
}
__device__ __forceinline__ uint32_t smem_u32(const void* p) {
    uint32_t a;
    asm("{ .reg .u64 t; cvta.to.shared.u64 t, %1; cvt.u32.u64 %0, t; }" : "=r"(a) : "l"(p));
    return a;
}

// ============================================================================
// GEMM: out[m,n] = sum_k A[m,k] * W[n,k] + bias[n]   (validated: 373us)
// Double-buffered smem: 1 sync per k-tile, STS overlapped with compute.
// MODE 0: A = x, z selects K/Q/V. K,Q -> [B,H,T,hd]; V (z==2) -> TRANSPOSED
//         [bh][d][t] so attention's AV phase gets V^T naturally.
// MODE 1: A = g_Y, out layout [M, C] (final projection into d_out)
// ============================================================================
#define TS_ 132   // smem row stride (floats)

template<int MODE>
__global__ void __launch_bounds__(256, 2) gemm_kernel(
    const float* __restrict__ A,
    const float* __restrict__ W0, const float* __restrict__ W1, const float* __restrict__ W2,
    const float* __restrict__ bias0, const float* __restrict__ bias1, const float* __restrict__ bias2,
    float* __restrict__ outp)
{
    __shared__ __align__(16) float As[2][16 * TS_];
    __shared__ __align__(16) float Bs[2][16 * TS_];

    const float* W; const float* bias; float* out;
    if (MODE == 0) {
        int z = blockIdx.z;
        W    = (z==0) ? W0    : ((z==1) ? W1    : W2);
        bias = (z==0) ? bias0 : ((z==1) ? bias1 : bias2);
        out  = (z==0) ? g_K   : ((z==1) ? g_Q   : g_V);
    } else {
        W = W0; bias = bias0; out = outp;
    }
    const float* Ap = (MODE == 0) ? A : (const float*)g_Y;

    int tid = threadIdx.x;
    int tx = tid & 15, ty = tid >> 4;
    int m0 = blockIdx.y * 128, n0 = blockIdx.x * 128;

    u64 acc[8][4];
    #pragma unroll
    for (int i = 0; i < 8; i++)
        #pragma unroll
        for (int j = 0; j < 4; j++) acc[i][j] = 0ull;

    int r0_ = tid >> 2,            c4_0 = tid & 3;
    int r1_ = (tid + 256) >> 2,    c4_1 = (tid + 256) & 3;

    float4 fA0, fA1, fW0, fW1;
    fA0 = *(const float4*)&Ap[(m0 + r0_) * C_ + c4_0 * 4];
    fW0 = *(const float4*)&W [(n0 + r0_) * C_ + c4_0 * 4];
    fA1 = *(const float4*)&Ap[(m0 + r1_) * C_ + c4_1 * 4];
    fW1 = *(const float4*)&W [(n0 + r1_) * C_ + c4_1 * 4];

    {
        float* as = As[0]; float* bs = Bs[0];
        as[(c4_0*4+0)*TS_ + r0_] = fA0.x; as[(c4_0*4+1)*TS_ + r0_] = fA0.y;
        as[(c4_0*4+2)*TS_ + r0_] = fA0.z; as[(c4_0*4+3)*TS_ + r0_] = fA0.w;
        bs[(c4_0*4+0)*TS_ + r0_] = fW0.x; bs[(c4_0*4+1)*TS_ + r0_] = fW0.y;
        bs[(c4_0*4+2)*TS_ + r0_] = fW0.z; bs[(c4_0*4+3)*TS_ + r0_] = fW0.w;
        as[(c4_1*4+0)*TS_ + r1_] = fA1.x; as[(c4_1*4+1)*TS_ + r1_] = fA1.y;
        as[(c4_1*4+2)*TS_ + r1_] = fA1.z; as[(c4_1*4+3)*TS_ + r1_] = fA1.w;
        bs[(c4_1*4+0)*TS_ + r1_] = fW1.x; bs[(c4_1*4+1)*TS_ + r1_] = fW1.y;
        bs[(c4_1*4+2)*TS_ + r1_] = fW1.z; bs[(c4_1*4+3)*TS_ + r1_] = fW1.w;
    }

    int buf = 0;
    #pragma unroll 1
    for (int k0 = 0; k0 < C_; k0 += 16) {
        __syncthreads();
        const bool hasnext = (k0 + 16 < C_);
        if (hasnext) {
            fA0 = *(const float4*)&Ap[(m0 + r0_) * C_ + k0 + 16 + c4_0 * 4];
            fW0 = *(const float4*)&W [(n0 + r0_) * C_ + k0 + 16 + c4_0 * 4];
            fA1 = *(const float4*)&Ap[(m0 + r1_) * C_ + k0 + 16 + c4_1 * 4];
            fW1 = *(const float4*)&W [(n0 + r1_) * C_ + k0 + 16 + c4_1 * 4];
        }
        const float* as = As[buf];
        const float* bs = Bs[buf];
        #pragma unroll
        for (int k = 0; k < 16; k++) {
            ulonglong2 b01 = *(const ulonglong2*)&bs[k*TS_ + tx*8];
            ulonglong2 b23 = *(const ulonglong2*)&bs[k*TS_ + tx*8 + 4];
            float4 a03 = *(const float4*)&as[k*TS_ + ty*8];
            float4 a47 = *(const float4*)&as[k*TS_ + ty*8 + 4];
            float av[8] = {a03.x, a03.y, a03.z, a03.w, a47.x, a47.y, a47.z, a47.w};
            #pragma unroll
            for (int i = 0; i < 8; i++) {
                u64 a2 = pack2(av[i], av[i]);
                acc[i][0] = fma2(a2, b01.x, acc[i][0]);
                acc[i][1] = fma2(a2, b01.y, acc[i][1]);
                acc[i][2] = fma2(a2, b23.x, acc[i][2]);
                acc[i][3] = fma2(a2, b23.y, acc[i][3]);
            }
        }
        if (hasnext) {
            float* asn = As[buf^1]; float* bsn = Bs[buf^1];
            asn[(c4_0*4+0)*TS_ + r0_] = fA0.x; asn[(c4_0*4+1)*TS_ + r0_] = fA0.y;
            asn[(c4_0*4+2)*TS_ + r0_] = fA0.z; asn[(c4_0*4+3)*TS_ + r0_] = fA0.w;
            bsn[(c4_0*4+0)*TS_ + r0_] = fW0.x; bsn[(c4_0*4+1)*TS_ + r0_] = fW0.y;
            bsn[(c4_0*4+2)*TS_ + r0_] = fW0.z; bsn[(c4_0*4+3)*TS_ + r0_] = fW0.w;
            asn[(c4_1*4+0)*TS_ + r1_] = fA1.x; asn[(c4_1*4+1)*TS_ + r1_] = fA1.y;
            asn[(c4_1*4+2)*TS_ + r1_] = fA1.z; asn[(c4_1*4+3)*TS_ + r1_] = fA1.w;
            bsn[(c4_1*4+0)*TS_ + r1_] = fW1.x; bsn[(c4_1*4+1)*TS_ + r1_] = fW1.y;
            bsn[(c4_1*4+2)*TS_ + r1_] = fW1.z; bsn[(c4_1*4+3)*TS_ + r1_] = fW1.w;
        }
        buf ^= 1;
    }

    int n_base = n0 + tx * 8;
    float4 bb0 = *(const float4*)&bias[n_base];
    float4 bb1 = *(const float4*)&bias[n_base + 4];
    #pragma unroll
    for (int i = 0; i < 8; i++) {
        int mm = m0 + ty*8 + i;
        float2 v0 = unpack2(acc[i][0]), v1 = unpack2(acc[i][1]);
        float2 v2 = unpack2(acc[i][2]), v3 = unpack2(acc[i][3]);
        float vals[8] = {v0.x + bb0.x, v0.y + bb0.y, v1.x + bb0.z, v1.y + bb0.w,
                         v2.x + bb1.x, v2.y + bb1.y, v3.x + bb1.z, v3.y + bb1.w};
        if (MODE == 0) {
            int bi = mm / T_;
            int tq = mm - bi * T_;
            int h = n_base >> 6, d = n_base & 63;
            if (blockIdx.z == 2) {
                // V^T: [bh][d][t]
                float* pv = out + (((size_t)bi * H_ + h) * 64 + d) * T_ + tq;
                #pragma unroll
                for (int c = 0; c < 8; c++) pv[(size_t)c * T_] = vals[c];
            } else {
                float* p = out + ((((size_t)bi * H_ + h) * T_ + tq) << 6) + d;
                *(float4*)p       = make_float4(vals[0], vals[1], vals[2], vals[3]);
                *(float4*)(p + 4) = make_float4(vals[4], vals[5], vals[6], vals[7]);
            }
        } else {
            float* p = out + (size_t)mm * C_ + n_base;
            *(float4*)p       = make_float4(vals[0], vals[1], vals[2], vals[3]);
            *(float4*)(p + 4) = make_float4(vals[4], vals[5], vals[6], vals[7]);
        }
    }
}

// ============================================================================
// GEMM-structured attention, cp.async pipelined, 2 barriers/chunk.
// Block = 64 query rows (tile ti, quarter j = 3-(qb&3), heavy-first), 256 thr.
// Thread (tx,ty): queries ty4..+3, keys/out-dims tx4..+3.
// QK: pairwise-over-d FFMA2 (K natural [k][d]).
// AV: pairwise-over-k FFMA2 (V^T [d][k] from global transposed layout;
//     S natural [q][k]) -- ZERO broadcast MOVs anywhere in the hot loops.
// K/V double-buffered via cp.async. No-max softmax (validated ~1e-6).
// Smem (floats): Qs 0, Ks{0,1} 4096/8192, Vt{0,1} 12288/16384, Ss 20480.
// ============================================================================
__global__ void __launch_bounds__(256, 2) attn_kernel()
{
    extern __shared__ __align__(16) float sm[];
    const uint32_t sb = smem_u32(sm);
    float* Qs = sm;
    float* Ss = sm + 20480;

    const int tid = threadIdx.x;
    const int tx  = tid & 15;
    const int ty  = tid >> 4;
    const int tx4 = tx * 4, ty4 = ty * 4;

    const int bh = blockIdx.y;                 // b*12 + h
    const int qb = blockIdx.x;                 // 0..39
    const int ti = qb >> 2;                    // tile 0..9
    const int j  = 3 - (qb & 3);               // quarter, heavy-first
    const int r0 = j * 64;

    const float* Qb = g_Q + (size_t)bh * T_ * HD_;
    const float* Kb = g_K + (size_t)bh * T_ * HD_;
    const float* Vb = g_V + (size_t)bh * HD_ * T_;   // [d][t]

    const int ldrow = tid >> 4;        // base row 0..15 (+16i)
    const int ldc   = tid & 15;        // 16B chunk 0..15

    // ---- prologue: Q tile + chunk0 K + chunk0 V^T ----
    #pragma unroll
    for (int i = 0; i < 4; i++) {
        int row = ldrow + 16*i;
        int qslot = (ldc ^ (row & 15)) & 15;
        int kslot = (ldc ^ (row >> 2)) & 15;
        cpa16(sb + (uint32_t)((row*64 + qslot*4) << 2),
              Qb + (size_t)(ti*256 + r0 + row)*HD_ + ldc*4);
        cpa16(sb + (uint32_t)((4096 + row*64 + kslot*4) << 2),
              Kb + (size_t)row*HD_ + ldc*4);
        cpa16(sb + (uint32_t)((12288 + row*64 + kslot*4) << 2),
              Vb + (size_t)row*T_ + ldc*4);                     // d=row, t=ldc*4
    }
    cpa_commit();

    u64 oacc[4][4];
    #pragma unroll
    for (int qi = 0; qi < 4; qi++)
        #pragma unroll
        for (int di = 0; di < 4; di++) oacc[qi][di] = 0ull;
    float lsum[4] = {0.f, 0.f, 0.f, 0.f};

    cpa_wait0();
    __syncthreads();

    const int NCH = 10 * (j + 1);
    int kt = 0, cj = 0, cur = 0;
    const float SCL = 0.125f * 1.4426950408889634f;   // (1/sqrt(64)) * log2(e)

    #pragma unroll 1
    for (int u = 0; u < NCH; u++) {
        const bool diag = (cj == j);
        const bool last = (u == NCH - 1);
        int nkt = kt, ncj = cj + 1;
        if (ncj > j) { ncj = 0; nkt = kt + 1; }

        // issue next chunk's K (natural) and V^T into the other buffers
        if (!last) {
            const int kg = nkt*256 + ncj*64;
            const int ko = cur ? 4096 : 8192;
            const int vo = cur ? 12288 : 16384;
            #pragma unroll
            for (int i = 0; i < 4; i++) {
                int row = ldrow + 16*i;
                int kslot = (ldc ^ (row >> 2)) & 15;
                cpa16(sb + (uint32_t)((ko + row*64 + kslot*4) << 2),
                      Kb + (size_t)(kg + row)*HD_ + ldc*4);
                cpa16(sb + (uint32_t)((vo + row*64 + kslot*4) << 2),
                      Vb + (size_t)row*T_ + kg + ldc*4);        // d=row, t=kg+ldc*4
            }
        }
        cpa_commit();

        const float* Kc = sm + (cur ? 8192 : 4096);
        const float* Vc = sm + (cur ? 16384 : 12288);

        // ---- QK^T: pairwise over d ----
        u64 sacc[4][4];
        #pragma unroll
        for (int qi = 0; qi < 4; qi++)
            #pragma unroll
            for (int ki = 0; ki < 4; ki++) sacc[qi][ki] = 0ull;

        #pragma unroll 8
        for (int c4 = 0; c4 < 16; c4++) {
            const int ks = ((c4 ^ tx) & 15) << 2;
            ulonglong2 kf[4];
            #pragma unroll
            for (int ki = 0; ki < 4; ki++)
                kf[ki] = *(const ulonglong2*)&Kc[(tx4+ki)*64 + ks];
            ulonglong2 qf[4];
            #pragma unroll
            for (int qi = 0; qi < 4; qi++) {
                int q = ty4 + qi;
                qf[qi] = *(const ulonglong2*)&Qs[q*64 + (((c4 ^ q) & 15) << 2)];
            }
            #pragma unroll
            for (int qi = 0; qi < 4; qi++)
                #pragma unroll
                for (int ki = 0; ki < 4; ki++) {
                    sacc[qi][ki] = fma2(qf[qi].x, kf[ki].x, sacc[qi][ki]);
                    sacc[qi][ki] = fma2(qf[qi].y, kf[ki].y, sacc[qi][ki]);
                }
        }

        // ---- softmax (no max) + store S natural [q][k] (swizzled by ty) ----
        #pragma unroll
        for (int qi = 0; qi < 4; qi++) {
            float pv[4];
            #pragma unroll
            for (int ki = 0; ki < 4; ki++) {
                float2 f = unpack2(sacc[qi][ki]);
                float s = (f.x + f.y) * SCL;
                float p;
                if (diag) p = (ty4 + qi >= tx4 + ki) ? ex2f_(s) : 0.f;
                else      p = ex2f_(s);
                pv[ki] = p;
                lsum[qi] += p;
            }
            *(float4*)&Ss[(ty4+qi)*64 + (((tx ^ ty) & 15) << 2)] =
                make_float4(pv[0], pv[1], pv[2], pv[3]);
        }

        cpa_wait0();
        __syncthreads();   // A: Ss visible + next K/V landed

        // ---- AV: pairwise over k (V^T in smem, S natural) ----
        #pragma unroll 8
        for (int kc4 = 0; kc4 < 16; kc4++) {
            const int vs = ((kc4 ^ tx) & 15) << 2;
            ulonglong2 vf[4];
            #pragma unroll
            for (int di = 0; di < 4; di++)
                vf[di] = *(const ulonglong2*)&Vc[(tx4+di)*64 + vs];
            const int ss = ((kc4 ^ ty) & 15) << 2;
            ulonglong2 sf[4];
            #pragma unroll
            for (int qi = 0; qi < 4; qi++)
                sf[qi] = *(const ulonglong2*)&Ss[(ty4+qi)*64 + ss];
            #pragma unroll
            for (int qi = 0; qi < 4; qi++)
                #pragma unroll
                for (int di = 0; di < 4; di++) {
                    oacc[qi][di] = fma2(sf[qi].x, vf[di].x, oacc[qi][di]);
                    oacc[qi][di] = fma2(sf[qi].y, vf[di].y, oacc[qi][di]);
                }
        }
        __syncthreads();   // B: AV done; Ss/Kc/Vc free

        cur ^= 1; kt = nkt; cj = ncj;
    }

    // ---- epilogue: reduce l across tx lanes, merge pairs, write O ----
    #pragma unroll
    for (int qi = 0; qi < 4; qi++) {
        float l = lsum[qi];
        l += __shfl_xor_sync(0xffffffffu, l, 1);
        l += __shfl_xor_sync(0xffffffffu, l, 2);
        l += __shfl_xor_sync(0xffffffffu, l, 4);
        l += __shfl_xor_sync(0xffffffffu, l, 8);
        lsum[qi] = 1.0f / l;
    }
    const int b = bh / H_, h = bh - (bh / H_) * H_;
    #pragma unroll
    for (int qi = 0; qi < 4; qi++) {
        int tg = ti*256 + r0 + ty4 + qi;
        float o[4];
        #pragma unroll
        for (int di = 0; di < 4; di++) {
            float2 f = unpack2(oacc[qi][di]);
            o[di] = (f.x + f.y) * lsum[qi];
        }
        *(float4*)&g_Y[((size_t)(b * T_ + tg)) * C_ + h * HD_ + tx4] =
            make_float4(o[0], o[1], o[2], o[3]);
    }
}

// ============================================================================
extern "C" void kernel_launch(void* const* d_in, const int* in_sizes, int n_in,
                              void* d_out, int out_size)
{
    (void)in_sizes; (void)n_in; (void)out_size;
    const float* x  = (const float*)d_in[0];
    const float* Wk = (const float*)d_in[1];
    const float* bk = (const float*)d_in[2];
    const float* Wq = (const float*)d_in[3];
    const float* bq = (const float*)d_in[4];
    const float* Wv = (const float*)d_in[5];
    const float* bv = (const float*)d_in[6];
    const float* Wp = (const float*)d_in[7];
    const float* bp = (const float*)d_in[8];
    float* out = (float*)d_out;

    const int attn_smem = 24576 * sizeof(float);   // 98304 B
    cudaFuncSetAttribute(attn_kernel, cudaFuncAttributeMaxDynamicSharedMemorySize, attn_smem);

    gemm_kernel<0><<<dim3(C_/128, M_/128, 3), 256>>>(x, Wk, Wq, Wv, bk, bq, bv, nullptr);
    attn_kernel<<<dim3(40, B_*H_), 256, attn_smem>>>();
    gemm_kernel<1><<<dim3(C_/128, M_/128, 1), 256>>>(nullptr, Wp, Wp, Wp, bp, bp, bp, out);
}

// round 15
// speedup vs baseline: 1.0626x; 1.0626x over previous
#include <cuda_runtime.h>
#include <cstdint>

typedef unsigned long long u64;

#define B_  2
#define T_  2560
#define C_  768
#define H_  12
#define HD_ 64
#define M_  (B_*T_)   // 5120

// ---- scratch (static device arrays; no allocation) ----
__device__ float g_Q[B_*H_*T_*HD_];
__device__ float g_K[B_*H_*T_*HD_];
__device__ float g_V[B_*H_*T_*HD_];
__device__ float g_Y[B_*T_*C_];

// ---- packed f32x2 helpers (Blackwell FFMA2) ----
__device__ __forceinline__ u64 fma2(u64 a, u64 b, u64 c) {
    u64 d; asm("fma.rn.f32x2 %0, %1, %2, %3;" : "=l"(d) : "l"(a), "l"(b), "l"(c)); return d;
}
__device__ __forceinline__ u64 pack2(float x, float y) {
    u64 d; asm("mov.b64 %0, {%1, %2};" : "=l"(d) : "f"(x), "f"(y)); return d;
}
__device__ __forceinline__ float2 unpack2(u64 v) {
    float2 r; asm("mov.b64 {%0, %1}, %2;" : "=f"(r.x), "=f"(r.y) : "l"(v)); return r;
}
__device__ __forceinline__ float ex2f_(float x) {
    float y; asm("ex2.approx.ftz.f32 %0, %1;" : "=f"(y) : "f"(x)); return y;
}
__device__ __forceinline__ void cpa16(uint32_t dst, const void* src) {
    asm volatile("cp.async.ca.shared.global [%0], [%1], 16;" :: "r"(dst), "l"(src) : "memory");
}
__device__ __forceinline__ void cpa_commit() {
    asm volatile("cp.async.commit_group;" ::: "memory");
}
__device__ __forceinline__ void cpa_wait0() {
    asm volatile("cp.async.wait_group 0;" ::: "memory");
}
__device__ __forceinline__ uint32_t smem_u32(const void* p) {
    uint32_t a;
    asm("{ .reg .u64 t; cvta.to.shared.u64 t, %1; cvt.u32.u64 %0, t; }" : "=r"(a) : "l"(p));
    return a;
}

// ============================================================================
// GEMM: out[m,n] = sum_k A[m,k] * W[n,k] + bias[n]   (validated: 373us)
// Double-buffered smem: 1 sync per k-tile, STS overlapped with compute.
// MODE 0: A = x, three outputs (z selects K/Q/V weights), out layout [B,H,T,hd]
// MODE 1: A = g_Y, out layout [M, C] (final projection into d_out)
// ============================================================================
#define TS_ 132   // smem row stride (floats)

template<int MODE>
__global__ void __launch_bounds__(256, 2) gemm_kernel(
    const float* __restrict__ A,
    const float* __restrict__ W0, const float* __restrict__ W1, const float* __restrict__ W2,
    const float* __restrict__ bias0, const float* __restrict__ bias1, const float* __restrict__ bias2,
    float* __restrict__ outp)
{
    __shared__ __align__(16) float As[2][16 * TS_];
    __shared__ __align__(16) float Bs[2][16 * TS_];

    const float* W; const float* bias; float* out;
    if (MODE == 0) {
        int z = blockIdx.z;
        W    = (z==0) ? W0    : ((z==1) ? W1    : W2);
        bias = (z==0) ? bias0 : ((z==1) ? bias1 : bias2);
        out  = (z==0) ? g_K   : ((z==1) ? g_Q   : g_V);
    } else {
        W = W0; bias = bias0; out = outp;
    }
    const float* Ap = (MODE == 0) ? A : (const float*)g_Y;

    int tid = threadIdx.x;
    int tx = tid & 15, ty = tid >> 4;
    int m0 = blockIdx.y * 128, n0 = blockIdx.x * 128;

    u64 acc[8][4];
    #pragma unroll
    for (int i = 0; i < 8; i++)
        #pragma unroll
        for (int j = 0; j < 4; j++) acc[i][j] = 0ull;

    int r0_ = tid >> 2,            c4_0 = tid & 3;
    int r1_ = (tid + 256) >> 2,    c4_1 = (tid + 256) & 3;

    float4 fA0, fA1, fW0, fW1;
    fA0 = *(const float4*)&Ap[(m0 + r0_) * C_ + c4_0 * 4];
    fW0 = *(const float4*)&W [(n0 + r0_) * C_ + c4_0 * 4];
    fA1 = *(const float4*)&Ap[(m0 + r1_) * C_ + c4_1 * 4];
    fW1 = *(const float4*)&W [(n0 + r1_) * C_ + c4_1 * 4];

    {
        float* as = As[0]; float* bs = Bs[0];
        as[(c4_0*4+0)*TS_ + r0_] = fA0.x; as[(c4_0*4+1)*TS_ + r0_] = fA0.y;
        as[(c4_0*4+2)*TS_ + r0_] = fA0.z; as[(c4_0*4+3)*TS_ + r0_] = fA0.w;
        bs[(c4_0*4+0)*TS_ + r0_] = fW0.x; bs[(c4_0*4+1)*TS_ + r0_] = fW0.y;
        bs[(c4_0*4+2)*TS_ + r0_] = fW0.z; bs[(c4_0*4+3)*TS_ + r0_] = fW0.w;
        as[(c4_1*4+0)*TS_ + r1_] = fA1.x; as[(c4_1*4+1)*TS_ + r1_] = fA1.y;
        as[(c4_1*4+2)*TS_ + r1_] = fA1.z; as[(c4_1*4+3)*TS_ + r1_] = fA1.w;
        bs[(c4_1*4+0)*TS_ + r1_] = fW1.x; bs[(c4_1*4+1)*TS_ + r1_] = fW1.y;
        bs[(c4_1*4+2)*TS_ + r1_] = fW1.z; bs[(c4_1*4+3)*TS_ + r1_] = fW1.w;
    }

    int buf = 0;
    #pragma unroll 1
    for (int k0 = 0; k0 < C_; k0 += 16) {
        __syncthreads();
        const bool hasnext = (k0 + 16 < C_);
        if (hasnext) {
            fA0 = *(const float4*)&Ap[(m0 + r0_) * C_ + k0 + 16 + c4_0 * 4];
            fW0 = *(const float4*)&W [(n0 + r0_) * C_ + k0 + 16 + c4_0 * 4];
            fA1 = *(const float4*)&Ap[(m0 + r1_) * C_ + k0 + 16 + c4_1 * 4];
            fW1 = *(const float4*)&W [(n0 + r1_) * C_ + k0 + 16 + c4_1 * 4];
        }
        const float* as = As[buf];
        const float* bs = Bs[buf];
        #pragma unroll
        for (int k = 0; k < 16; k++) {
            ulonglong2 b01 = *(const ulonglong2*)&bs[k*TS_ + tx*8];
            ulonglong2 b23 = *(const ulonglong2*)&bs[k*TS_ + tx*8 + 4];
            float4 a03 = *(const float4*)&as[k*TS_ + ty*8];
            float4 a47 = *(const float4*)&as[k*TS_ + ty*8 + 4];
            float av[8] = {a03.x, a03.y, a03.z, a03.w, a47.x, a47.y, a47.z, a47.w};
            #pragma unroll
            for (int i = 0; i < 8; i++) {
                u64 a2 = pack2(av[i], av[i]);
                acc[i][0] = fma2(a2, b01.x, acc[i][0]);
                acc[i][1] = fma2(a2, b01.y, acc[i][1]);
                acc[i][2] = fma2(a2, b23.x, acc[i][2]);
                acc[i][3] = fma2(a2, b23.y, acc[i][3]);
            }
        }
        if (hasnext) {
            float* asn = As[buf^1]; float* bsn = Bs[buf^1];
            asn[(c4_0*4+0)*TS_ + r0_] = fA0.x; asn[(c4_0*4+1)*TS_ + r0_] = fA0.y;
            asn[(c4_0*4+2)*TS_ + r0_] = fA0.z; asn[(c4_0*4+3)*TS_ + r0_] = fA0.w;
            bsn[(c4_0*4+0)*TS_ + r0_] = fW0.x; bsn[(c4_0*4+1)*TS_ + r0_] = fW0.y;
            bsn[(c4_0*4+2)*TS_ + r0_] = fW0.z; bsn[(c4_0*4+3)*TS_ + r0_] = fW0.w;
            asn[(c4_1*4+0)*TS_ + r1_] = fA1.x; asn[(c4_1*4+1)*TS_ + r1_] = fA1.y;
            asn[(c4_1*4+2)*TS_ + r1_] = fA1.z; asn[(c4_1*4+3)*TS_ + r1_] = fA1.w;
            bsn[(c4_1*4+0)*TS_ + r1_] = fW1.x; bsn[(c4_1*4+1)*TS_ + r1_] = fW1.y;
            bsn[(c4_1*4+2)*TS_ + r1_] = fW1.z; bsn[(c4_1*4+3)*TS_ + r1_] = fW1.w;
        }
        buf ^= 1;
    }

    int n_base = n0 + tx * 8;
    float4 bb0 = *(const float4*)&bias[n_base];
    float4 bb1 = *(const float4*)&bias[n_base + 4];
    #pragma unroll
    for (int i = 0; i < 8; i++) {
        int mm = m0 + ty*8 + i;
        float* p;
        if (MODE == 0) {
            int bi = mm / T_;
            int tq = mm - bi * T_;
            int h = n_base >> 6, d = n_base & 63;
            p = out + ((((size_t)bi * H_ + h) * T_ + tq) << 6) + d;   // [B,H,T,hd]
        } else {
            p = out + (size_t)mm * C_ + n_base;                       // [M,C]
        }
        float2 v0 = unpack2(acc[i][0]), v1 = unpack2(acc[i][1]);
        float2 v2 = unpack2(acc[i][2]), v3 = unpack2(acc[i][3]);
        *(float4*)p       = make_float4(v0.x + bb0.x, v0.y + bb0.y, v1.x + bb0.z, v1.y + bb0.w);
        *(float4*)(p + 4) = make_float4(v2.x + bb1.x, v2.y + bb1.y, v3.x + bb1.z, v3.y + bb1.w);
    }
}

// ============================================================================
// GEMM-structured attention, cp.async pipelined, ONE barrier per chunk.
// Block = 64 query rows (tile ti, quarter j = 3-(qb&3), heavy-first), 256 thr.
// Thread (tx,ty): queries ty4..+3, keys/out-dims tx4..+3.
// QK: pairwise-over-d FFMA2 (K natural [k][d]); AV: broadcast-over-S.
// KEY FACT: S element (k,q) is written by (tx=k/4, ty=q/4) and read only by
// threads with the same ty -> S round-trip is WARP-LOCAL -> __syncwarp().
// The single block barrier (after AV + cpa_wait) orders: AV-done before next
// chunk's cpa overwrites V[cur], and all threads' prefetch before next QK.
// No-max softmax (validated rel_err ~1e-6 across R6-R14).
// Smem (floats): Qs 0, Ks{0,1} 4096/8192, Vs{0,1} 12288/16384, Ss 20480.
// ============================================================================
__global__ void __launch_bounds__(256, 2) attn_kernel()
{
    extern __shared__ __align__(16) float sm[];
    const uint32_t sb = smem_u32(sm);
    float* Qs = sm;
    float* Ss = sm + 20480;

    const int tid = threadIdx.x;
    const int tx  = tid & 15;
    const int ty  = tid >> 4;
    const int tx4 = tx * 4, ty4 = ty * 4;

    const int bh = blockIdx.y;                 // b*12 + h
    const int qb = blockIdx.x;                 // 0..39
    const int ti = qb >> 2;                    // tile 0..9
    const int j  = 3 - (qb & 3);               // quarter, heavy-first
    const int r0 = j * 64;

    const float* Qb = g_Q + (size_t)bh * T_ * HD_;
    const float* Kb = g_K + (size_t)bh * T_ * HD_;
    const float* Vb = g_V + (size_t)bh * T_ * HD_;

    const int ldrow = tid >> 4;        // base row 0..15 (+16i)
    const int ldc   = tid & 15;        // 16B chunk 0..15

    // ---- prologue: Q tile + chunk0 K/V via cp.async ----
    #pragma unroll
    for (int i = 0; i < 4; i++) {
        int row = ldrow + 16*i;
        int qslot = (ldc ^ (row & 15)) & 15;
        int kslot = (ldc ^ (row >> 2)) & 15;
        cpa16(sb + (uint32_t)((row*64 + qslot*4) << 2),
              Qb + (size_t)(ti*256 + r0 + row)*HD_ + ldc*4);
        cpa16(sb + (uint32_t)((4096 + row*64 + kslot*4) << 2),
              Kb + (size_t)row*HD_ + ldc*4);
        cpa16(sb + (uint32_t)((12288 + row*64 + kslot*4) << 2),
              Vb + (size_t)row*HD_ + ldc*4);
    }
    cpa_commit();

    u64 oacc[4][2];
    #pragma unroll
    for (int qi = 0; qi < 4; qi++) { oacc[qi][0] = 0ull; oacc[qi][1] = 0ull; }
    float lsum[4] = {0.f, 0.f, 0.f, 0.f};

    cpa_wait0();
    __syncthreads();

    const int NCH = 10 * (j + 1);
    int kt = 0, cj = 0, cur = 0;
    const float SCL = 0.125f * 1.4426950408889634f;   // (1/sqrt(64)) * log2(e)

    #pragma unroll 1
    for (int u = 0; u < NCH; u++) {
        const bool diag = (cj == j);
        const bool last = (u == NCH - 1);
        int nkt = kt, ncj = cj + 1;
        if (ncj > j) { ncj = 0; nkt = kt + 1; }

        // issue next chunk's K/V into the other buffers (not read this chunk)
        if (!last) {
            const int kg = nkt*256 + ncj*64;
            const int ko = cur ? 4096 : 8192;
            const int vo = cur ? 12288 : 16384;
            #pragma unroll
            for (int i = 0; i < 4; i++) {
                int row = ldrow + 16*i;
                int kslot = (ldc ^ (row >> 2)) & 15;
                cpa16(sb + (uint32_t)((ko + row*64 + kslot*4) << 2),
                      Kb + (size_t)(kg + row)*HD_ + ldc*4);
                cpa16(sb + (uint32_t)((vo + row*64 + kslot*4) << 2),
                      Vb + (size_t)(kg + row)*HD_ + ldc*4);
            }
        }
        cpa_commit();

        const float* Kc = sm + (cur ? 8192 : 4096);
        const float* Vc = sm + (cur ? 16384 : 12288);

        // ---- QK^T: pairwise over d ----
        u64 sacc[4][4];
        #pragma unroll
        for (int qi = 0; qi < 4; qi++)
            #pragma unroll
            for (int ki = 0; ki < 4; ki++) sacc[qi][ki] = 0ull;

        #pragma unroll 8
        for (int c4 = 0; c4 < 16; c4++) {
            const int ks = ((c4 ^ tx) & 15) << 2;
            ulonglong2 kf[4];
            #pragma unroll
            for (int ki = 0; ki < 4; ki++)
                kf[ki] = *(const ulonglong2*)&Kc[(tx4+ki)*64 + ks];
            ulonglong2 qf[4];
            #pragma unroll
            for (int qi = 0; qi < 4; qi++) {
                int q = ty4 + qi;
                qf[qi] = *(const ulonglong2*)&Qs[q*64 + (((c4 ^ q) & 15) << 2)];
            }
            #pragma unroll
            for (int qi = 0; qi < 4; qi++)
                #pragma unroll
                for (int ki = 0; ki < 4; ki++) {
                    sacc[qi][ki] = fma2(qf[qi].x, kf[ki].x, sacc[qi][ki]);
                    sacc[qi][ki] = fma2(qf[qi].y, kf[ki].y, sacc[qi][ki]);
                }
        }

        // ---- softmax (no max) + store S transposed [k][q] (warp-local) ----
        #pragma unroll
        for (int ki = 0; ki < 4; ki++) {
            float pv[4];
            #pragma unroll
            for (int qi = 0; qi < 4; qi++) {
                float2 f = unpack2(sacc[qi][ki]);
                float s = (f.x + f.y) * SCL;
                float p;
                if (diag) p = (ty4 + qi >= tx4 + ki) ? ex2f_(s) : 0.f;
                else      p = ex2f_(s);
                pv[qi] = p;
                lsum[qi] += p;
            }
            *(float4*)&Ss[(tx4+ki)*64 + (((ty ^ tx) & 15) << 2)] =
                make_float4(pv[0], pv[1], pv[2], pv[3]);
        }
        __syncwarp();      // S produced/consumed entirely within this warp

        // ---- AV: broadcast over S, V natural ----
        #pragma unroll 8
        for (int k = 0; k < 64; k++) {
            float4 a = *(const float4*)&Ss[k*64 + (((ty ^ (k >> 2)) & 15) << 2)];
            ulonglong2 v = *(const ulonglong2*)&Vc[k*64 + (((tx ^ (k >> 2)) & 15) << 2)];
            float av[4] = {a.x, a.y, a.z, a.w};
            #pragma unroll
            for (int qi = 0; qi < 4; qi++) {
                u64 a2 = pack2(av[qi], av[qi]);
                oacc[qi][0] = fma2(a2, v.x, oacc[qi][0]);
                oacc[qi][1] = fma2(a2, v.y, oacc[qi][1]);
            }
        }

        cpa_wait0();       // prefetch had the whole chunk to land
        __syncthreads();   // single barrier: AV done + next K/V visible to all

        cur ^= 1; kt = nkt; cj = ncj;
    }

    // ---- epilogue: reduce l across tx lanes, write O ----
    #pragma unroll
    for (int qi = 0; qi < 4; qi++) {
        float l = lsum[qi];
        l += __shfl_xor_sync(0xffffffffu, l, 1);
        l += __shfl_xor_sync(0xffffffffu, l, 2);
        l += __shfl_xor_sync(0xffffffffu, l, 4);
        l += __shfl_xor_sync(0xffffffffu, l, 8);
        lsum[qi] = 1.0f / l;
    }
    const int b = bh / H_, h = bh - (bh / H_) * H_;
    #pragma unroll
    for (int qi = 0; qi < 4; qi++) {
        int tg = ti*256 + r0 + ty4 + qi;
        float2 f0 = unpack2(oacc[qi][0]);
        float2 f1 = unpack2(oacc[qi][1]);
        float inv = lsum[qi];
        *(float4*)&g_Y[((size_t)(b * T_ + tg)) * C_ + h * HD_ + tx4] =
            make_float4(f0.x*inv, f0.y*inv, f1.x*inv, f1.y*inv);
    }
}

// ============================================================================
extern "C" void kernel_launch(void* const* d_in, const int* in_sizes, int n_in,
                              void* d_out, int out_size)
{
    (void)in_sizes; (void)n_in; (void)out_size;
    const float* x  = (const float*)d_in[0];
    const float* Wk = (const float*)d_in[1];
    const float* bk = (const float*)d_in[2];
    const float* Wq = (const float*)d_in[3];
    const float* bq = (const float*)d_in[4];
    const float* Wv = (const float*)d_in[5];
    const float* bv = (const float*)d_in[6];
    const float* Wp = (const float*)d_in[7];
    const float* bp = (const float*)d_in[8];
    float* out = (float*)d_out;

    const int attn_smem = 24576 * sizeof(float);   // 98304 B
    cudaFuncSetAttribute(attn_kernel, cudaFuncAttributeMaxDynamicSharedMemorySize, attn_smem);

    gemm_kernel<0><<<dim3(C_/128, M_/128, 3), 256>>>(x, Wk, Wq, Wv, bk, bq, bv, nullptr);
    attn_kernel<<<dim3(40, B_*H_), 256, attn_smem>>>();
    gemm_kernel<1><<<dim3(C_/128, M_/128, 1), 256>>>(nullptr, Wp, Wp, Wp, bp, bp, bp, out);
}